// round 16
// baseline (speedup 1.0000x reference)
#include <cuda_runtime.h>
#include <cuda_bf16.h>
#include <cstdint>
#include <cstddef>

#define SW(x) ((x) ^ (((x) >> 3) & 0x70))

// ---------------- static device scratch (no allocations) -------------------
__device__ __nv_bfloat16 g_emb_bf[25165824];          // [m=t*64+b][768]
__device__ __nv_bfloat16 g_Wih_bf[2][786432];         // [dir][1024][768]
__device__ __nv_bfloat16 g_Whh_bf[2][262144];         // [dir][1024][256]
__device__ __nv_bfloat16 g_Wlin[4608];                // [9][512]
__device__ float         g_xg[2][33554432];           // [dir][m][1024]
__device__ __nv_bfloat16 g_hall[2][8388608];          // [dir][m][256]
__device__ __nv_bfloat16 g_hcur[2][2][16384];         // [parity][dir][b*256+k]
__device__ float         g_em[294912];                // [m][9]
__device__ float         g_res[64];
__device__ int           g_len[64];
__device__ unsigned      g_cnt;
__device__ volatile unsigned g_gen;

// ---------------- helpers --------------------------------------------------
__device__ __forceinline__ void ldsm4(unsigned* r, unsigned a) {
    asm volatile("ldmatrix.sync.aligned.m8n8.x4.shared.b16 {%0,%1,%2,%3},[%4];"
                 : "=r"(r[0]), "=r"(r[1]), "=r"(r[2]), "=r"(r[3]) : "r"(a));
}
__device__ __forceinline__ void mmaf(float* c, const unsigned* a, unsigned b0, unsigned b1) {
    asm volatile("mma.sync.aligned.m16n8k16.row.col.f32.bf16.bf16.f32 "
                 "{%0,%1,%2,%3},{%4,%5,%6,%7},{%8,%9},{%0,%1,%2,%3};"
                 : "+f"(c[0]), "+f"(c[1]), "+f"(c[2]), "+f"(c[3])
                 : "r"(a[0]), "r"(a[1]), "r"(a[2]), "r"(a[3]), "r"(b0), "r"(b1));
}
__device__ __forceinline__ float sigf(float x) {
    float e; asm("ex2.approx.f32 %0, %1;" : "=f"(e) : "f"(-1.4426950408889634f * x));
    float r; asm("rcp.approx.f32 %0, %1;" : "=f"(r) : "f"(1.0f + e));
    return r;
}
__device__ __forceinline__ float tanha(float x) {
    float r; asm("tanh.approx.f32 %0, %1;" : "=f"(r) : "f"(x)); return r;
}
__device__ __forceinline__ void load8(float* o, const __nv_bfloat16* p) {
    uint4 u = *(const uint4*)p;
    const __nv_bfloat162* h = (const __nv_bfloat162*)&u;
#pragma unroll
    for (int i = 0; i < 4; i++) { float2 f = __bfloat1622float2(h[i]); o[2*i] = f.x; o[2*i+1] = f.y; }
}
__device__ __forceinline__ void grid_bar() {
    __syncthreads();
    if (threadIdx.x == 0) {
        unsigned old = g_gen;
        __threadfence();
        unsigned t = atomicAdd(&g_cnt, 1u);
        if (t == 63u) { g_cnt = 0u; __threadfence(); g_gen = old + 1u; }
        else { while (g_gen == old) {} }
        __threadfence();
    }
    __syncthreads();
}

// ---------------- mask sniff + lengths -------------------------------------
__global__ void k_mask(const unsigned char* mraw) {
    __shared__ int mode;
    if (threadIdx.x == 0) {
        if (mraw[1] == 1) mode = 0;            // bool/uint8
        else if (mraw[0] == 1) mode = 1;       // int32
        else mode = 2;                          // float32
    }
    __syncthreads();
    int b = threadIdx.x, c = 0;
    if (mode == 0) { for (int t = 0; t < 512; t++) c += (mraw[b*512+t] != 0); }
    else if (mode == 1) { const int* p = (const int*)mraw; for (int t = 0; t < 512; t++) c += (p[b*512+t] != 0); }
    else { const float* p = (const float*)mraw; for (int t = 0; t < 512; t++) c += (p[b*512+t] != 0.0f); }
    g_len[b] = c;
}

// ---------------- conversions ----------------------------------------------
__global__ __launch_bounds__(256) void k_conv_emb(const float* __restrict__ src) {
    int idx = blockIdx.x * 256 + threadIdx.x;          // < 6291456 float4s
    int m = idx / 192, e4 = idx - m * 192;
    int b = m & 63, t = m >> 6;
    float4 f = ((const float4*)src)[(b*512 + t)*192 + e4];
    __nv_bfloat162* d2 = (__nv_bfloat162*)(g_emb_bf + (size_t)m*768 + e4*4);
    d2[0] = __floats2bfloat162_rn(f.x, f.y);
    d2[1] = __floats2bfloat162_rn(f.z, f.w);
}
__global__ __launch_bounds__(256) void k_conv(const float* __restrict__ s, int which, int n4) {
    int idx = blockIdx.x * 256 + threadIdx.x;
    if (idx >= n4) return;
    __nv_bfloat16* d = (which == 0) ? g_Wih_bf[0] : (which == 1) ? g_Wih_bf[1] :
                       (which == 2) ? g_Whh_bf[0] : (which == 3) ? g_Whh_bf[1] : g_Wlin;
    float4 f = ((const float4*)s)[idx];
    __nv_bfloat162* d2 = (__nv_bfloat162*)(d + idx*4);
    d2[0] = __floats2bfloat162_rn(f.x, f.y);
    d2[1] = __floats2bfloat162_rn(f.z, f.w);
}

// ---------------- GEMM1: xg = x @ W_ih^T + b  (bf16 mma) --------------------
// A stage tile: 128 rows x 64 cols bf16 = 1024 x 16B chunks (8 per 128B row)
// B stage tile:  64 rows x 64 cols bf16 =  512 x 16B chunks
#define G1_LOAD(st, k0_) do {                                                     \
    unsigned baseA = sA + (st) * 16384;                                           \
    _Pragma("unroll")                                                             \
    for (int j_ = 0; j_ < 4; j_++) {                                              \
        int q_ = tid + 256*j_; int r_ = q_ >> 3, c_ = q_ & 7;                     \
        unsigned d_ = baseA + SW(r_*128 + c_*16);                                 \
        const __nv_bfloat16* g_ = Ag + (size_t)(m0 + r_)*768 + (k0_) + c_*8;      \
        asm volatile("cp.async.cg.shared.global [%0],[%1],16;" :: "r"(d_), "l"(g_)); } \
    { unsigned baseB = sB + (st) * 8192;                                          \
      _Pragma("unroll")                                                           \
      for (int j_ = 0; j_ < 2; j_++) {                                            \
        int q_ = tid + 256*j_; int r_ = q_ >> 3, c_ = q_ & 7;                     \
        unsigned d_ = baseB + SW(r_*128 + c_*16);                                 \
        const __nv_bfloat16* g_ = Wg + (size_t)(n0 + r_)*768 + (k0_) + c_*8;      \
        asm volatile("cp.async.cg.shared.global [%0],[%1],16;" :: "r"(d_), "l"(g_)); } } \
    asm volatile("cp.async.commit_group;"); } while (0)

__global__ __launch_bounds__(256) void k_gemm_xg(const float* __restrict__ bias0,
                                                 const float* __restrict__ bias1) {
    __shared__ __nv_bfloat16 As[2][8192];   // 128 x 64 per stage
    __shared__ __nv_bfloat16 Bs[2][4096];   // 64 x 64 per stage
    int dir = blockIdx.z;
    const __nv_bfloat16* Ag = g_emb_bf;
    const __nv_bfloat16* Wg = g_Wih_bf[dir];
    float* out = g_xg[dir];
    const float* bias = dir ? bias1 : bias0;
    int tid = threadIdx.x;
    int m0 = blockIdx.y * 128, n0 = blockIdx.x * 64;
    unsigned sA = (unsigned)__cvta_generic_to_shared(&As[0][0]);
    unsigned sB = (unsigned)__cvta_generic_to_shared(&Bs[0][0]);
    int w = tid >> 5, l = tid & 31;
    int wm = w >> 1, wn = w & 1;            // wm: 0..3 (32 rows), wn: 0..1 (32 cols)

    float acc[2][4][4];
#pragma unroll
    for (int a = 0; a < 2; a++)
#pragma unroll
        for (int b = 0; b < 4; b++)
#pragma unroll
            for (int c = 0; c < 4; c++) acc[a][b][c] = 0.0f;

    G1_LOAD(0, 0);
    for (int it = 0; it < 12; ++it) {
        int st = it & 1;
        if (it < 11) G1_LOAD((it + 1) & 1, (it + 1) * 64);
        if (it < 11) asm volatile("cp.async.wait_group 1;");
        else         asm volatile("cp.async.wait_group 0;");
        __syncthreads();
        unsigned aB = sA + st * 16384;
        unsigned bB = sB + st * 8192;
        unsigned bf[4][2][4];
#pragma unroll
        for (int kk2 = 0; kk2 < 2; kk2++)
#pragma unroll
            for (int nt = 0; nt < 4; nt++) {
                int nr = wn * 32 + nt * 8 + (l & 7);
                int cb = kk2 * 64 + (l >> 3) * 16;
                ldsm4(bf[nt][kk2], bB + SW(nr * 128 + cb));
            }
#pragma unroll
        for (int kk = 0; kk < 4; ++kk) {
            unsigned af[2][4];
#pragma unroll
            for (int mt = 0; mt < 2; mt++) {
                int r = wm * 32 + mt * 16 + (l & 15);
                int cb = kk * 32 + (l >> 4) * 16;
                ldsm4(af[mt], aB + SW(r * 128 + cb));
            }
#pragma unroll
            for (int mt = 0; mt < 2; mt++)
#pragma unroll
                for (int nt = 0; nt < 4; nt++)
                    mmaf(acc[mt][nt], af[mt],
                         bf[nt][kk >> 1][(kk & 1) * 2], bf[nt][kk >> 1][(kk & 1) * 2 + 1]);
        }
        __syncthreads();
    }
    // epilogue
#pragma unroll
    for (int mt = 0; mt < 2; mt++)
#pragma unroll
        for (int nt = 0; nt < 4; nt++) {
            int m = m0 + wm * 32 + mt * 16 + (l >> 2);
            int n = n0 + wn * 32 + nt * 8 + 2 * (l & 3);
            float b0 = bias[n], b1 = bias[n + 1];
            float2 v0 = make_float2(acc[mt][nt][0] + b0, acc[mt][nt][1] + b1);
            float2 v1 = make_float2(acc[mt][nt][2] + b0, acc[mt][nt][3] + b1);
            *(float2*)(out + (size_t)m * 1024 + n) = v0;
            *(float2*)(out + (size_t)(m + 8) * 1024 + n) = v1;
        }
}

// ---------------- persistent LSTM (both directions) ------------------------
__global__ __launch_bounds__(256) void k_lstm() {
    __shared__ __nv_bfloat16 hs[16384];     // 32 KB: h as [kc4][64][64], W staging [kc4][32][64]
    __shared__ float gbuf[2112];            // [64][33]
    __shared__ float cst[512];              // [64][8]
    int bx = blockIdx.x;
    int dir = bx >> 5, ks = bx & 31, k0 = ks * 8;
    int tid = threadIdx.x, w = tid >> 5, l = tid & 31;
    int wm = w >> 1, wn = w & 1;            // wm: 0..3 (m16), wn: 0..1 (n16)
    unsigned sh = (unsigned)__cvta_generic_to_shared(hs);

    // init: zero h_cur parity0 slice + cell state
    {
        __nv_bfloat16 z = __float2bfloat16(0.0f);
        for (int q = tid; q < 512; q += 256) {
            int b = q >> 3, j = q & 7;
            g_hcur[0][dir][b * 256 + k0 + j] = z;
            cst[q] = 0.0f;
        }
        __threadfence();
    }

    // stage W_hh slice -> smem -> registers (held for entire scan)
    {
        const __nv_bfloat16* Wg = g_Whh_bf[dir];
#pragma unroll
        for (int j4 = 0; j4 < 4; j4++) {
            int q = tid + 256 * j4;                 // 1024 chunks of 16B
            int c = q >> 5, ch = q & 31;            // c: local row 0..31
            int k = ch * 8, kc = k >> 6, ko = k & 63;
            unsigned d = sh + kc * 4096 + SW(c * 128 + ko * 2);
            const __nv_bfloat16* g = Wg + (size_t)((c >> 3) * 256 + k0 + (c & 7)) * 256 + k;
            asm volatile("cp.async.cg.shared.global [%0],[%1],16;" :: "r"(d), "l"(g));
        }
        asm volatile("cp.async.commit_group;");
        asm volatile("cp.async.wait_group 0;");
        __syncthreads();
    }
    unsigned wfr[2][8][4];
#pragma unroll
    for (int kk2 = 0; kk2 < 8; kk2++)
#pragma unroll
        for (int nt = 0; nt < 2; nt++) {
            int lr = wn * 16 + nt * 8 + (l & 7);
            int cb = (kk2 & 1) * 64 + (l >> 3) * 16;
            ldsm4(wfr[nt][kk2], sh + (kk2 >> 1) * 4096 + SW(lr * 128 + cb));
        }
    __syncthreads();

    const float* xg = g_xg[dir];
    for (int step = 0; step < 512; ++step) {
        int t = dir ? (511 - step) : step;
        grid_bar();

        // xg preload (direct LDG, latency hidden behind h-stage + mma)
        float xv[2][4];
#pragma unroll
        for (int pp = 0; pp < 2; ++pp) {
            int p = tid + pp * 256; int b = p >> 3, j = p & 7;
            const float* x = xg + (size_t)(t * 64 + b) * 1024 + k0 + j;
            xv[pp][0] = x[0]; xv[pp][1] = x[256]; xv[pp][2] = x[512]; xv[pp][3] = x[768];
        }

        // h stage: 64x256 bf16 -> smem [kc4][64][64]
        const __nv_bfloat16* hp = g_hcur[step & 1][dir];
#pragma unroll
        for (int j8 = 0; j8 < 8; j8++) {
            int q = tid + 256 * j8;                 // 2048 chunks of 16B
            int b = q >> 5, ch = q & 31;
            int k = ch * 8, kc = k >> 6, ko = k & 63;
            unsigned d = sh + kc * 8192 + SW(b * 128 + ko * 2);
            asm volatile("cp.async.cg.shared.global [%0],[%1],16;" :: "r"(d), "l"(hp + b * 256 + k));
        }
        asm volatile("cp.async.commit_group;");
        asm volatile("cp.async.wait_group 0;");
        __syncthreads();

        // gemm: C[64x32] = h[64x256] * Whh_slice^T
        float acc[2][4];
#pragma unroll
        for (int nt = 0; nt < 2; nt++)
#pragma unroll
            for (int c = 0; c < 4; c++) acc[nt][c] = 0.0f;
#pragma unroll
        for (int kk = 0; kk < 16; ++kk) {
            unsigned af[4];
            int r = wm * 16 + (l & 15);
            int cb = (kk & 3) * 32 + (l >> 4) * 16;
            ldsm4(af, sh + (kk >> 2) * 8192 + SW(r * 128 + cb));
            mmaf(acc[0], af, wfr[0][kk >> 1][(kk & 1) * 2], wfr[0][kk >> 1][(kk & 1) * 2 + 1]);
            mmaf(acc[1], af, wfr[1][kk >> 1][(kk & 1) * 2], wfr[1][kk >> 1][(kk & 1) * 2 + 1]);
        }
        __syncthreads();
#pragma unroll
        for (int nt = 0; nt < 2; nt++) {
            int m = wm * 16 + (l >> 2);
            int c = wn * 16 + nt * 8 + 2 * (l & 3);
            gbuf[m * 33 + c] = acc[nt][0]; gbuf[m * 33 + c + 1] = acc[nt][1];
            gbuf[(m + 8) * 33 + c] = acc[nt][2]; gbuf[(m + 8) * 33 + c + 1] = acc[nt][3];
        }
        __syncthreads();

        // epilogue: gates -> (c, h)
        __nv_bfloat16* hn = g_hcur[(step & 1) ^ 1][dir];
#pragma unroll
        for (int pp = 0; pp < 2; ++pp) {
            int p = tid + pp * 256; int b = p >> 3, j = p & 7;
            float ii = gbuf[b * 33 + j] + xv[pp][0];
            float ff = gbuf[b * 33 + 8 + j] + xv[pp][1];
            float gg = gbuf[b * 33 + 16 + j] + xv[pp][2];
            float oo = gbuf[b * 33 + 24 + j] + xv[pp][3];
            float c = sigf(ff) * cst[p] + sigf(ii) * tanha(gg);
            cst[p] = c;
            float h = sigf(oo) * tanha(c);
            __nv_bfloat16 hb = __float2bfloat16(h);
            hn[b * 256 + k0 + j] = hb;
            g_hall[dir][(size_t)(t * 64 + b) * 256 + k0 + j] = hb;
        }
        __threadfence();
    }
}

// ---------------- emissions: em = [h_f|h_b] @ W_lin^T + b_lin ---------------
__global__ __launch_bounds__(256) void k_em(const float* __restrict__ blin) {
    __shared__ __nv_bfloat16 Ws[4608];
    __shared__ float bl[9];
    int tid = threadIdx.x;
    for (int q = tid; q < 4608; q += 256) Ws[q] = g_Wlin[q];
    if (tid < 9) bl[tid] = blin[tid];
    __syncthreads();
    int w = tid >> 5, l = tid & 31;
    int m = blockIdx.x * 8 + w;
    float hf[8], hb[8];
    load8(hf, g_hall[0] + (size_t)m * 256 + l * 8);
    load8(hb, g_hall[1] + (size_t)m * 256 + l * 8);
#pragma unroll
    for (int lj = 0; lj < 9; lj++) {
        float a[8], bw[8];
        load8(a, Ws + lj * 512 + l * 8);
        load8(bw, Ws + lj * 512 + 256 + l * 8);
        float s = 0.0f;
#pragma unroll
        for (int i = 0; i < 8; i++) s += hf[i] * a[i] + hb[i] * bw[i];
#pragma unroll
        for (int off = 16; off; off >>= 1) s += __shfl_xor_sync(0xffffffffu, s, off);
        if (l == 0) g_em[(size_t)m * 9 + lj] = s + bl[lj];
    }
}

// ---------------- CRF: numerator + partition, per-batch warp ----------------
__global__ void k_crf(const float* __restrict__ st_, const float* __restrict__ en_,
                      const float* __restrict__ tr_, const int* __restrict__ lab_) {
    int b = blockIdx.x;
    int l = threadIdx.x;
    int j = (l < 9) ? l : 8;
    float trr[9];
#pragma unroll
    for (int i = 0; i < 9; i++) trr[i] = tr_[i * 9 + j];
    float enj = en_[j];
    int len = g_len[b];
    const int* lb = lab_ + b * 512;
    float s = (l < 9) ? (st_[j] + g_em[(size_t)b * 9 + l]) : -1e30f;
    float num = 0.0f;
    int tprev = 0;
    if (l == 0) { tprev = lb[0]; num = st_[tprev] + g_em[(size_t)b * 9 + tprev]; }
    for (int t = 1; t < 512; t++) {
        float em_j = (l < 9) ? g_em[((size_t)t * 64 + b) * 9 + l] : -1e30f;
        float v[9]; float mx = -1e30f;
#pragma unroll
        for (int i = 0; i < 9; i++) {
            v[i] = __shfl_sync(0xffffffffu, s, i) + trr[i];
            mx = fmaxf(mx, v[i]);
        }
        float sum = 0.0f;
#pragma unroll
        for (int i = 0; i < 9; i++) sum += __expf(v[i] - mx);
        float nxt = mx + __logf(sum) + em_j;
        bool act = (t < len);
        if (act && l < 9) s = nxt;
        if (l == 0 && act) {
            int tc = lb[t];
            num += tr_[tprev * 9 + tc] + g_em[((size_t)t * 64 + b) * 9 + tc];
            tprev = tc;
        }
    }
    float z = (l < 9) ? (s + enj) : -1e30f;
    float mx = z;
#pragma unroll
    for (int off = 16; off; off >>= 1) mx = fmaxf(mx, __shfl_xor_sync(0xffffffffu, mx, off));
    float sum = __expf(z - mx);
#pragma unroll
    for (int off = 16; off; off >>= 1) sum += __shfl_xor_sync(0xffffffffu, sum, off);
    float logZ = mx + __logf(sum);
    if (l == 0) {
        num += en_[lb[len - 1]];
        g_res[b] = logZ - num;
    }
}

__global__ void k_final(float* out) {
    __shared__ float sm[64];
    sm[threadIdx.x] = g_res[threadIdx.x];
    __syncthreads();
    if (threadIdx.x == 0) {
        float s = 0.0f;
        for (int i = 0; i < 64; i++) s += sm[i];
        out[0] = s / 64.0f;
    }
}

// ---------------- launch ----------------------------------------------------
extern "C" void kernel_launch(void* const* d_in, const int* in_sizes, int n_in,
                              void* d_out, int out_size) {
    const float* emb  = (const float*)d_in[0];
    const float* Wihf = (const float*)d_in[1];
    const float* Whhf = (const float*)d_in[2];
    const float* bf   = (const float*)d_in[3];
    const float* Wihb = (const float*)d_in[4];
    const float* Whhb = (const float*)d_in[5];
    const float* bb   = (const float*)d_in[6];
    const float* Wlin = (const float*)d_in[7];
    const float* blin = (const float*)d_in[8];
    const float* stt  = (const float*)d_in[9];
    const float* ent  = (const float*)d_in[10];
    const float* tr   = (const float*)d_in[11];
    const unsigned char* mask = (const unsigned char*)d_in[12];
    const int* lab    = (const int*)d_in[13];

    k_mask<<<1, 64>>>(mask);
    k_conv_emb<<<24576, 256>>>(emb);
    k_conv<<<768, 256>>>(Wihf, 0, 196608);
    k_conv<<<768, 256>>>(Wihb, 1, 196608);
    k_conv<<<256, 256>>>(Whhf, 2, 65536);
    k_conv<<<256, 256>>>(Whhb, 3, 65536);
    k_conv<<<5, 256>>>(Wlin, 4, 1152);
    k_gemm_xg<<<dim3(16, 256, 2), 256>>>(bf, bb);
    k_lstm<<<64, 256>>>();
    k_em<<<4096, 256>>>(blin);
    k_crf<<<64, 32>>>(stt, ent, tr, lab);
    k_final<<<1, 64>>>((float*)d_out);
}

// round 17
// speedup vs baseline: 1.1768x; 1.1768x over previous
#include <cuda_runtime.h>
#include <cuda_bf16.h>
#include <cstdint>
#include <cstddef>

#define SW(x) ((x) ^ (((x) >> 3) & 0x70))

// ---------------- static device scratch (no allocations) -------------------
__device__ __nv_bfloat16 g_emb_bf[25165824];          // [m=t*64+b][768]
__device__ __nv_bfloat16 g_Wih_bf[2][786432];         // [dir][1024][768]
__device__ __nv_bfloat16 g_Whh_bf[2][262144];         // [dir][1024][256]
__device__ __nv_bfloat16 g_Wlin[4608];                // [9][512]
__device__ float         g_xg[2][33554432];           // [dir][m][1024]
__device__ __nv_bfloat16 g_hall[2][8388608];          // [dir][m][256]
__device__ uint4         g_hfrag[2][2][2048];         // [parity][dir][(wm*16+kt)*32+lane]
__device__ float         g_em[294912];                // [m][9]
__device__ float         g_res[64];
__device__ int           g_len[64];
__device__ unsigned      g_cnt2[2];                   // per-dir monotonic arrival counters

// ---------------- helpers --------------------------------------------------
__device__ __forceinline__ void ldsm4(unsigned* r, unsigned a) {
    asm volatile("ldmatrix.sync.aligned.m8n8.x4.shared.b16 {%0,%1,%2,%3},[%4];"
                 : "=r"(r[0]), "=r"(r[1]), "=r"(r[2]), "=r"(r[3]) : "r"(a));
}
__device__ __forceinline__ void mmaf(float* c, const unsigned* a, unsigned b0, unsigned b1) {
    asm volatile("mma.sync.aligned.m16n8k16.row.col.f32.bf16.bf16.f32 "
                 "{%0,%1,%2,%3},{%4,%5,%6,%7},{%8,%9},{%0,%1,%2,%3};"
                 : "+f"(c[0]), "+f"(c[1]), "+f"(c[2]), "+f"(c[3])
                 : "r"(a[0]), "r"(a[1]), "r"(a[2]), "r"(a[3]), "r"(b0), "r"(b1));
}
__device__ __forceinline__ float sigf(float x) {
    float r; asm("tanh.approx.f32 %0, %1;" : "=f"(r) : "f"(0.5f * x));
    return 0.5f * r + 0.5f;
}
__device__ __forceinline__ float tanha(float x) {
    float r; asm("tanh.approx.f32 %0, %1;" : "=f"(r) : "f"(x)); return r;
}
__device__ __forceinline__ void load8(float* o, const __nv_bfloat16* p) {
    uint4 u = *(const uint4*)p;
    const __nv_bfloat162* h = (const __nv_bfloat162*)&u;
#pragma unroll
    for (int i = 0; i < 4; i++) { float2 f = __bfloat1622float2(h[i]); o[2*i] = f.x; o[2*i+1] = f.y; }
}
// fragment address (h value at batch b, hidden col c within 0..255)
__device__ __forceinline__ int frag_idx(int b, int c) {
    int wm = b >> 4, r = b & 15, kt = c >> 4, cc = c & 15;
    int lane = (r & 7) * 4 + ((cc & 7) >> 1);
    int reg  = ((cc & 8) >> 2) + ((r & 8) >> 3);
    return ((((wm * 16 + kt) * 32 + lane) * 4 + reg) * 2) + (cc & 1);   // bf16 index
}

// ---------------- mask sniff + lengths + counter reset ----------------------
__global__ void k_mask(const unsigned char* mraw) {
    __shared__ int mode;
    if (threadIdx.x < 2) g_cnt2[threadIdx.x] = 0u;
    if (threadIdx.x == 0) {
        if (mraw[1] == 1) mode = 0;            // bool/uint8
        else if (mraw[0] == 1) mode = 1;       // int32
        else mode = 2;                          // float32
    }
    __syncthreads();
    int b = threadIdx.x, c = 0;
    if (mode == 0) { for (int t = 0; t < 512; t++) c += (mraw[b*512+t] != 0); }
    else if (mode == 1) { const int* p = (const int*)mraw; for (int t = 0; t < 512; t++) c += (p[b*512+t] != 0); }
    else { const float* p = (const float*)mraw; for (int t = 0; t < 512; t++) c += (p[b*512+t] != 0.0f); }
    g_len[b] = c;
}

// ---------------- conversions ----------------------------------------------
__global__ __launch_bounds__(256) void k_conv_emb(const float* __restrict__ src) {
    int idx = blockIdx.x * 256 + threadIdx.x;          // < 6291456 float4s
    int m = idx / 192, e4 = idx - m * 192;
    int b = m & 63, t = m >> 6;
    float4 f = ((const float4*)src)[(b*512 + t)*192 + e4];
    __nv_bfloat162* d2 = (__nv_bfloat162*)(g_emb_bf + (size_t)m*768 + e4*4);
    d2[0] = __floats2bfloat162_rn(f.x, f.y);
    d2[1] = __floats2bfloat162_rn(f.z, f.w);
}
__device__ __forceinline__ __nv_bfloat16* conv_dst(int which) {
    return (which == 0) ? g_Wih_bf[0] : (which == 1) ? g_Wih_bf[1] :
           (which == 2) ? g_Whh_bf[0] : (which == 3) ? g_Whh_bf[1] : g_Wlin;
}
__global__ __launch_bounds__(256) void k_convW(const float* s1, const float* s2, const float* s3,
                                               int w1, int w2, int w3, int n1, int n2, int n3) {
    int idx = blockIdx.x * 256 + threadIdx.x;
    const float* s; __nv_bfloat16* d; int off;
    if (idx < n1)                { s = s1; d = conv_dst(w1); off = idx; }
    else if (idx < n1 + n2)      { s = s2; d = conv_dst(w2); off = idx - n1; }
    else if (idx < n1 + n2 + n3) { s = s3; d = conv_dst(w3); off = idx - n1 - n2; }
    else return;
    float4 f = ((const float4*)s)[off];
    __nv_bfloat162* d2 = (__nv_bfloat162*)(d + off * 4);
    d2[0] = __floats2bfloat162_rn(f.x, f.y);
    d2[1] = __floats2bfloat162_rn(f.z, f.w);
}

// ---------------- GEMM1: xg = x @ W_ih^T + b  (bf16 mma) --------------------
#define G1_LOAD(st, k0_) do {                                                     \
    unsigned baseA = sA + (st) * 16384;                                           \
    _Pragma("unroll")                                                             \
    for (int j_ = 0; j_ < 4; j_++) {                                              \
        int q_ = tid + 256*j_; int r_ = q_ >> 3, c_ = q_ & 7;                     \
        unsigned d_ = baseA + SW(r_*128 + c_*16);                                 \
        const __nv_bfloat16* g_ = Ag + (size_t)(m0 + r_)*768 + (k0_) + c_*8;      \
        asm volatile("cp.async.cg.shared.global [%0],[%1],16;" :: "r"(d_), "l"(g_)); } \
    { unsigned baseB = sB + (st) * 8192;                                          \
      _Pragma("unroll")                                                           \
      for (int j_ = 0; j_ < 2; j_++) {                                            \
        int q_ = tid + 256*j_; int r_ = q_ >> 3, c_ = q_ & 7;                     \
        unsigned d_ = baseB + SW(r_*128 + c_*16);                                 \
        const __nv_bfloat16* g_ = Wg + (size_t)(n0 + r_)*768 + (k0_) + c_*8;      \
        asm volatile("cp.async.cg.shared.global [%0],[%1],16;" :: "r"(d_), "l"(g_)); } } \
    asm volatile("cp.async.commit_group;"); } while (0)

__global__ __launch_bounds__(256) void k_gemm_xg(const float* __restrict__ bias0,
                                                 const float* __restrict__ bias1) {
    __shared__ __nv_bfloat16 As[2][8192];   // 128 x 64 per stage
    __shared__ __nv_bfloat16 Bs[2][4096];   // 64 x 64 per stage
    int dir = blockIdx.z;
    const __nv_bfloat16* Ag = g_emb_bf;
    const __nv_bfloat16* Wg = g_Wih_bf[dir];
    float* out = g_xg[dir];
    const float* bias = dir ? bias1 : bias0;
    int tid = threadIdx.x;
    int m0 = blockIdx.y * 128, n0 = blockIdx.x * 64;
    unsigned sA = (unsigned)__cvta_generic_to_shared(&As[0][0]);
    unsigned sB = (unsigned)__cvta_generic_to_shared(&Bs[0][0]);
    int w = tid >> 5, l = tid & 31;
    int wm = w >> 1, wn = w & 1;

    float acc[2][4][4];
#pragma unroll
    for (int a = 0; a < 2; a++)
#pragma unroll
        for (int b = 0; b < 4; b++)
#pragma unroll
            for (int c = 0; c < 4; c++) acc[a][b][c] = 0.0f;

    G1_LOAD(0, 0);
    for (int it = 0; it < 12; ++it) {
        int st = it & 1;
        if (it < 11) G1_LOAD((it + 1) & 1, (it + 1) * 64);
        if (it < 11) asm volatile("cp.async.wait_group 1;");
        else         asm volatile("cp.async.wait_group 0;");
        __syncthreads();
        unsigned aB = sA + st * 16384;
        unsigned bB = sB + st * 8192;
        unsigned bf[4][2][4];
#pragma unroll
        for (int kk2 = 0; kk2 < 2; kk2++)
#pragma unroll
            for (int nt = 0; nt < 4; nt++) {
                int nr = wn * 32 + nt * 8 + (l & 7);
                int cb = kk2 * 64 + (l >> 3) * 16;
                ldsm4(bf[nt][kk2], bB + SW(nr * 128 + cb));
            }
#pragma unroll
        for (int kk = 0; kk < 4; ++kk) {
            unsigned af[2][4];
#pragma unroll
            for (int mt = 0; mt < 2; mt++) {
                int r = wm * 32 + mt * 16 + (l & 15);
                int cb = kk * 32 + (l >> 4) * 16;
                ldsm4(af[mt], aB + SW(r * 128 + cb));
            }
#pragma unroll
            for (int mt = 0; mt < 2; mt++)
#pragma unroll
                for (int nt = 0; nt < 4; nt++)
                    mmaf(acc[mt][nt], af[mt],
                         bf[nt][kk >> 1][(kk & 1) * 2], bf[nt][kk >> 1][(kk & 1) * 2 + 1]);
        }
        __syncthreads();
    }
#pragma unroll
    for (int mt = 0; mt < 2; mt++)
#pragma unroll
        for (int nt = 0; nt < 4; nt++) {
            int m = m0 + wm * 32 + mt * 16 + (l >> 2);
            int n = n0 + wn * 32 + nt * 8 + 2 * (l & 3);
            float b0 = bias[n], b1 = bias[n + 1];
            float2 v0 = make_float2(acc[mt][nt][0] + b0, acc[mt][nt][1] + b1);
            float2 v1 = make_float2(acc[mt][nt][2] + b0, acc[mt][nt][3] + b1);
            *(float2*)(out + (size_t)m * 1024 + n) = v0;
            *(float2*)(out + (size_t)(m + 8) * 1024 + n) = v1;
        }
}

// ---------------- persistent LSTM (both directions) ------------------------
__global__ __launch_bounds__(256) void k_lstm() {
    __shared__ __nv_bfloat16 ws[8192];      // 16 KB: W staging only
    __shared__ float gbuf[2112];            // [64][33]
    __shared__ float cst[512];
    int bx = blockIdx.x;
    int dir = bx >> 5, ks = bx & 31, k0 = ks * 8;
    int tid = threadIdx.x, w = tid >> 5, l = tid & 31;
    int wm = w >> 1, wn = w & 1;
    unsigned sh = (unsigned)__cvta_generic_to_shared(ws);

    // stage W_hh slice -> smem (swizzled) -> register fragments (held all scan)
    {
        const __nv_bfloat16* Wg = g_Whh_bf[dir];
#pragma unroll
        for (int j4 = 0; j4 < 4; j4++) {
            int q = tid + 256 * j4;                 // 1024 chunks of 16B
            int c = q >> 5, ch = q & 31;
            int k = ch * 8, kc = k >> 6, ko = k & 63;
            unsigned d = sh + kc * 4096 + SW(c * 128 + ko * 2);
            const __nv_bfloat16* g = Wg + (size_t)((c >> 3) * 256 + k0 + (c & 7)) * 256 + k;
            asm volatile("cp.async.cg.shared.global [%0],[%1],16;" :: "r"(d), "l"(g));
        }
        asm volatile("cp.async.commit_group;");
        asm volatile("cp.async.wait_group 0;");
        __syncthreads();
    }
    unsigned wfr[2][8][4];
#pragma unroll
    for (int kk2 = 0; kk2 < 8; kk2++)
#pragma unroll
        for (int nt = 0; nt < 2; nt++) {
            int lr = wn * 16 + nt * 8 + (l & 7);
            int cb = (kk2 & 1) * 64 + (l >> 3) * 16;
            ldsm4(wfr[nt][kk2], sh + (kk2 >> 1) * 4096 + SW(lr * 128 + cb));
        }

    // init: zero cell state + parity-0 fragment slice, then arrive
    {
        __nv_bfloat16* fp = (__nv_bfloat16*)&g_hfrag[0][dir][0];
        __nv_bfloat16 z = __float2bfloat16(0.0f);
        for (int q = tid; q < 512; q += 256) {
            int b = q >> 3, j = q & 7;
            cst[q] = 0.0f;
            fp[frag_idx(b, k0 + j)] = z;
        }
        __threadfence();
        __syncthreads();
        if (tid == 0) atomicAdd(&g_cnt2[dir], 1u);
    }

    const float* xg = g_xg[dir];
    volatile unsigned* cnt = &g_cnt2[dir];

    for (int step = 0; step < 512; ++step) {
        int t = dir ? (511 - step) : step;

        // xg prefetch (independent of barrier; in flight during spin)
        float xv[2][4];
#pragma unroll
        for (int pp = 0; pp < 2; ++pp) {
            int p = tid + pp * 256; int b = p >> 3, j = p & 7;
            const float* x = xg + (size_t)(t * 64 + b) * 1024 + k0 + j;
            xv[pp][0] = x[0]; xv[pp][1] = x[256]; xv[pp][2] = x[512]; xv[pp][3] = x[768];
        }

        // wait: all 32 blocks of this dir produced h for this step
        if (tid == 0) {
            unsigned tgt = 32u * (unsigned)(step + 1);
            while (*cnt < tgt) {}
        }
        __syncthreads();

        // A fragments (h) via direct L2 loads — no smem round trip
        const uint4* fb = g_hfrag[step & 1][dir] + (wm * 16) * 32 + l;
        unsigned af[16][4];
#pragma unroll
        for (int kt = 0; kt < 16; ++kt) {
            const uint4* p = fb + kt * 32;
            asm volatile("ld.global.cg.v4.u32 {%0,%1,%2,%3},[%4];"
                         : "=r"(af[kt][0]), "=r"(af[kt][1]), "=r"(af[kt][2]), "=r"(af[kt][3])
                         : "l"(p));
        }
        float acc[2][4];
#pragma unroll
        for (int nt = 0; nt < 2; nt++)
#pragma unroll
            for (int c = 0; c < 4; c++) acc[nt][c] = 0.0f;
#pragma unroll
        for (int kt = 0; kt < 16; ++kt) {
            mmaf(acc[0], af[kt], wfr[0][kt >> 1][(kt & 1) * 2], wfr[0][kt >> 1][(kt & 1) * 2 + 1]);
            mmaf(acc[1], af[kt], wfr[1][kt >> 1][(kt & 1) * 2], wfr[1][kt >> 1][(kt & 1) * 2 + 1]);
        }
        // gbuf exchange (prev-step reads separated by end-of-step sync)
#pragma unroll
        for (int nt = 0; nt < 2; nt++) {
            int m = wm * 16 + (l >> 2);
            int c = wn * 16 + nt * 8 + 2 * (l & 3);
            gbuf[m * 33 + c] = acc[nt][0]; gbuf[m * 33 + c + 1] = acc[nt][1];
            gbuf[(m + 8) * 33 + c] = acc[nt][2]; gbuf[(m + 8) * 33 + c + 1] = acc[nt][3];
        }
        __syncthreads();

        // epilogue: gates -> (c, h); h stored pre-fragmented for next step
        __nv_bfloat16* fp = (__nv_bfloat16*)&g_hfrag[(step & 1) ^ 1][dir][0];
#pragma unroll
        for (int pp = 0; pp < 2; ++pp) {
            int p = tid + pp * 256; int b = p >> 3, j = p & 7;
            float ii = gbuf[b * 33 + j]      + xv[pp][0];
            float ff = gbuf[b * 33 + 8 + j]  + xv[pp][1];
            float gg = gbuf[b * 33 + 16 + j] + xv[pp][2];
            float oo = gbuf[b * 33 + 24 + j] + xv[pp][3];
            float c = sigf(ff) * cst[p] + sigf(ii) * tanha(gg);
            cst[p] = c;
            float h = sigf(oo) * tanha(c);
            __nv_bfloat16 hb = __float2bfloat16(h);
            g_hall[dir][(size_t)(t * 64 + b) * 256 + k0 + j] = hb;
            fp[frag_idx(b, k0 + j)] = hb;
        }
        __threadfence();
        __syncthreads();
        if (tid == 0) atomicAdd(&g_cnt2[dir], 1u);
    }
}

// ---------------- emissions: em = [h_f|h_b] @ W_lin^T + b_lin ---------------
__global__ __launch_bounds__(256) void k_em(const float* __restrict__ blin) {
    __shared__ __nv_bfloat16 Ws[4608];
    __shared__ float bl[9];
    int tid = threadIdx.x;
    for (int q = tid; q < 4608; q += 256) Ws[q] = g_Wlin[q];
    if (tid < 9) bl[tid] = blin[tid];
    __syncthreads();
    int w = tid >> 5, l = tid & 31;
    int m = blockIdx.x * 8 + w;
    float hf[8], hb[8];
    load8(hf, g_hall[0] + (size_t)m * 256 + l * 8);
    load8(hb, g_hall[1] + (size_t)m * 256 + l * 8);
#pragma unroll
    for (int lj = 0; lj < 9; lj++) {
        float a[8], bw[8];
        load8(a, Ws + lj * 512 + l * 8);
        load8(bw, Ws + lj * 512 + 256 + l * 8);
        float s = 0.0f;
#pragma unroll
        for (int i = 0; i < 8; i++) s += hf[i] * a[i] + hb[i] * bw[i];
#pragma unroll
        for (int off = 16; off; off >>= 1) s += __shfl_xor_sync(0xffffffffu, s, off);
        if (l == 0) g_em[(size_t)m * 9 + lj] = s + bl[lj];
    }
}

// ---------------- CRF: numerator + partition, per-batch warp ----------------
__global__ void k_crf(const float* __restrict__ st_, const float* __restrict__ en_,
                      const float* __restrict__ tr_, const int* __restrict__ lab_) {
    int b = blockIdx.x;
    int l = threadIdx.x;
    int j = (l < 9) ? l : 8;
    float trr[9];
#pragma unroll
    for (int i = 0; i < 9; i++) trr[i] = tr_[i * 9 + j];
    float enj = en_[j];
    int len = g_len[b];
    const int* lb = lab_ + b * 512;
    float s = (l < 9) ? (st_[j] + g_em[(size_t)b * 9 + l]) : -1e30f;
    float num = 0.0f;
    int tprev = 0;
    if (l == 0) { tprev = lb[0]; num = st_[tprev] + g_em[(size_t)b * 9 + tprev]; }
    for (int t = 1; t < 512; t++) {
        float em_j = (l < 9) ? g_em[((size_t)t * 64 + b) * 9 + l] : -1e30f;
        float v[9]; float mx = -1e30f;
#pragma unroll
        for (int i = 0; i < 9; i++) {
            v[i] = __shfl_sync(0xffffffffu, s, i) + trr[i];
            mx = fmaxf(mx, v[i]);
        }
        float sum = 0.0f;
#pragma unroll
        for (int i = 0; i < 9; i++) sum += __expf(v[i] - mx);
        float nxt = mx + __logf(sum) + em_j;
        bool act = (t < len);
        if (act && l < 9) s = nxt;
        if (l == 0 && act) {
            int tc = lb[t];
            num += tr_[tprev * 9 + tc] + g_em[((size_t)t * 64 + b) * 9 + tc];
            tprev = tc;
        }
    }
    float z = (l < 9) ? (s + enj) : -1e30f;
    float mx = z;
#pragma unroll
    for (int off = 16; off; off >>= 1) mx = fmaxf(mx, __shfl_xor_sync(0xffffffffu, mx, off));
    float sum = __expf(z - mx);
#pragma unroll
    for (int off = 16; off; off >>= 1) sum += __shfl_xor_sync(0xffffffffu, sum, off);
    float logZ = mx + __logf(sum);
    if (l == 0) {
        num += en_[lb[len - 1]];
        g_res[b] = logZ - num;
    }
}

__global__ void k_final(float* out) {
    __shared__ float sm[64];
    sm[threadIdx.x] = g_res[threadIdx.x];
    __syncthreads();
    if (threadIdx.x == 0) {
        float s = 0.0f;
        for (int i = 0; i < 64; i++) s += sm[i];
        out[0] = s / 64.0f;
    }
}

// ---------------- launch ----------------------------------------------------
extern "C" void kernel_launch(void* const* d_in, const int* in_sizes, int n_in,
                              void* d_out, int out_size) {
    const float* emb  = (const float*)d_in[0];
    const float* Wihf = (const float*)d_in[1];
    const float* Whhf = (const float*)d_in[2];
    const float* bf   = (const float*)d_in[3];
    const float* Wihb = (const float*)d_in[4];
    const float* Whhb = (const float*)d_in[5];
    const float* bb   = (const float*)d_in[6];
    const float* Wlin = (const float*)d_in[7];
    const float* blin = (const float*)d_in[8];
    const float* stt  = (const float*)d_in[9];
    const float* ent  = (const float*)d_in[10];
    const float* tr   = (const float*)d_in[11];
    const unsigned char* mask = (const unsigned char*)d_in[12];
    const int* lab    = (const int*)d_in[13];

    // launch order chosen so k_lstm is the 6th launch (ncu -s 5 -c 1 profiles it)
    k_mask<<<1, 64>>>(mask);                                           // 1
    k_conv_emb<<<24576, 256>>>(emb);                                   // 2
    k_convW<<<1024, 256>>>(Wihf, Whhf, nullptr, 0, 2, 4, 196608, 65536, 0);   // 3
    k_convW<<<1029, 256>>>(Wihb, Whhb, Wlin, 1, 3, 4, 196608, 65536, 1152);   // 4
    k_gemm_xg<<<dim3(16, 256, 2), 256>>>(bf, bb);                      // 5
    k_lstm<<<64, 256>>>();                                             // 6  <- profiled
    k_em<<<4096, 256>>>(blin);
    k_crf<<<64, 32>>>(stt, ent, tr, lab);
    k_final<<<1, 64>>>((float*)d_out);
}